// round 1
// baseline (speedup 1.0000x reference)
#include <cuda_runtime.h>
#include <math.h>

// ---------------------------------------------------------------------------
// Problem constants (fixed shapes for StandardPointHead_27728308862989)
// ---------------------------------------------------------------------------
#define B_   2
#define C_   256
#define H_   128
#define W_   128
#define Q_   32768
#define HD_  256
#define HW_  (H_*W_)            // 16384
#define M_CONV (B_*HW_)         // 65536
#define K_CONV (C_*9)           // 2304
#define N_CONV (2*HD_)          // 512 (coef | freq)
#define M_MLP  (4*B_*Q_)        // 262144

// ---------------------------------------------------------------------------
// Scratch (device globals; no allocations anywhere)
// ---------------------------------------------------------------------------
__device__ float g_wconv[(size_t)K_CONV * N_CONV];          // [k][n] combined conv weights
__device__ float g_bconv[N_CONV];
__device__ float g_col[(size_t)M_CONV * K_CONV];            // im2col, 604 MB
__device__ float g_convout[(size_t)M_CONV * N_CONV];        // [pixel][512]
__device__ float g_U[(size_t)M_MLP * 256];                  // ping
__device__ float g_V[(size_t)M_MLP * 256];                  // pong
__device__ float g_pred[(size_t)M_MLP * 2];
__device__ float g_area[M_MLP];                             // [s][b][q]

// ---------------------------------------------------------------------------
// K0: combine + transpose conv weights into [k = c*9+tap][n = oc (coef|freq)]
// ---------------------------------------------------------------------------
__global__ void prep_weights_kernel(const float* __restrict__ cw, const float* __restrict__ cb,
                                    const float* __restrict__ fw, const float* __restrict__ fb)
{
    int t = blockIdx.x * blockDim.x + threadIdx.x;
    if (t < N_CONV) g_bconv[t] = (t < HD_) ? cb[t] : fb[t - HD_];
    if (t < K_CONV * N_CONV) {
        int n = t & (N_CONV - 1);
        int k = t >> 9;
        g_wconv[t] = (n < HD_) ? cw[(size_t)n * K_CONV + k]
                               : fw[(size_t)(n - HD_) * K_CONV + k];
    }
}

// ---------------------------------------------------------------------------
// K1: im2col with zero padding ('SAME').  row m = b*HW + y*W + x, col = c*9+tap
// Thread t -> (m = t>>8, c = t&255): writes 9 contiguous floats (coalesced).
// ---------------------------------------------------------------------------
__global__ void im2col_kernel(const float* __restrict__ feat)
{
    int t = blockIdx.x * blockDim.x + threadIdx.x;
    if (t >= M_CONV * C_) return;
    int c = t & (C_ - 1);
    int m = t >> 8;
    int x = m & (W_ - 1);
    int y = (m >> 7) & (H_ - 1);
    int b = m >> 14;
    const float* fp = feat + (((size_t)b * C_ + c) << 14);
    float* cp = g_col + (size_t)m * K_CONV + c * 9;
#pragma unroll
    for (int dy = 0; dy < 3; dy++) {
        int yy = y + dy - 1;
#pragma unroll
        for (int dx = 0; dx < 3; dx++) {
            int xx = x + dx - 1;
            float v = (yy >= 0 && yy < H_ && xx >= 0 && xx < W_) ? fp[yy * W_ + xx] : 0.0f;
            cp[dy * 3 + dx] = v;
        }
    }
}

// ---------------------------------------------------------------------------
// SGEMM: C[M,N] = act(A[M,K] @ W[K,N] + bias).  128x128 block tile, BK=16,
// 256 threads, 8x8 register tile.  M%128==0, N%128==0, K%16==0.
// ---------------------------------------------------------------------------
__launch_bounds__(256, 2)
__global__ void sgemm_kernel(const float* __restrict__ A, const float* __restrict__ W,
                             const float* __restrict__ bias, float* __restrict__ C,
                             int M, int N, int K, int doRelu)
{
    __shared__ float As[16][129];   // [k][m], padded to kill store conflicts
    __shared__ float Ws[16][128];   // [k][n]
    const int tid = threadIdx.x;
    const int tx = tid & 15;
    const int ty = tid >> 4;
    const int bm = blockIdx.y * 128;
    const int bn = blockIdx.x * 128;

    float acc[8][8];
#pragma unroll
    for (int i = 0; i < 8; i++)
#pragma unroll
        for (int j = 0; j < 8; j++) acc[i][j] = 0.0f;

    for (int k0 = 0; k0 < K; k0 += 16) {
#pragma unroll
        for (int r = 0; r < 2; r++) {                 // A tile: 128x16 = 512 float4 loads
            int idx = tid + r * 256;
            int row = idx >> 2;
            int c4  = (idx & 3) << 2;
            float4 v = *reinterpret_cast<const float4*>(&A[(size_t)(bm + row) * K + k0 + c4]);
            As[c4 + 0][row] = v.x; As[c4 + 1][row] = v.y;
            As[c4 + 2][row] = v.z; As[c4 + 3][row] = v.w;
        }
#pragma unroll
        for (int r = 0; r < 2; r++) {                 // W tile: 16x128
            int idx = tid + r * 256;
            int row = idx >> 5;
            int c4  = (idx & 31) << 2;
            *reinterpret_cast<float4*>(&Ws[row][c4]) =
                *reinterpret_cast<const float4*>(&W[(size_t)(k0 + row) * N + bn + c4]);
        }
        __syncthreads();
#pragma unroll
        for (int kk = 0; kk < 16; kk++) {
            float a[8], bb[8];
#pragma unroll
            for (int i = 0; i < 8; i++) a[i] = As[kk][ty * 8 + i];
#pragma unroll
            for (int j = 0; j < 8; j++) bb[j] = Ws[kk][tx * 8 + j];
#pragma unroll
            for (int i = 0; i < 8; i++)
#pragma unroll
                for (int j = 0; j < 8; j++) acc[i][j] = fmaf(a[i], bb[j], acc[i][j]);
        }
        __syncthreads();
    }
#pragma unroll
    for (int i = 0; i < 8; i++) {
        const int m = bm + ty * 8 + i;
#pragma unroll
        for (int j = 0; j < 8; j++) {
            const int n = bn + tx * 8 + j;
            float v = acc[i][j] + bias[n];
            if (doRelu) v = fmaxf(v, 0.0f);
            C[(size_t)m * N + n] = v;
        }
    }
}

// ---------------------------------------------------------------------------
// K3: per (shift, b, q) row build X = q_coef * [cos(pi*qf) | sin(pi*qf)].
// One warp per row; lane handles k = lane + 32*j (j<4).
// ---------------------------------------------------------------------------
__global__ void prepare_kernel(const float* __restrict__ pc,
                               const float* __restrict__ phase_w)
{
    int gw = (blockIdx.x * blockDim.x + threadIdx.x) >> 5;
    int lane = threadIdx.x & 31;
    if (gw >= M_MLP) return;
    int q = gw & (Q_ - 1);
    int b = (gw >> 15) & 1;
    int s = gw >> 16;
    float vx = (s & 2) ? 1.0f : -1.0f;
    float vy = (s & 1) ? 1.0f : -1.0f;

    float p0 = pc[((size_t)(b * Q_ + q)) * 2 + 0];
    float p1 = pc[((size_t)(b * Q_ + q)) * 2 + 1];
    float c0 = fminf(fmaxf(p0 + (vx * (1.0f / 128.0f) + 1e-6f), -1.0f + 1e-6f), 1.0f - 1e-6f);
    float c1 = fminf(fmaxf(p1 + (vy * (1.0f / 128.0f) + 1e-6f), -1.0f + 1e-6f), 1.0f - 1e-6f);
    // nearest index, jnp.round = round-half-even = rintf
    int iy = (int)rintf(((c0 + 1.0f) * 128.0f - 1.0f) * 0.5f);
    int ix = (int)rintf(((c1 + 1.0f) * 128.0f - 1.0f) * 0.5f);
    iy = min(max(iy, 0), H_ - 1);
    ix = min(max(ix, 0), W_ - 1);
    float qcy = -0.9921875f + 0.015625f * (float)iy;   // -1 + 1/H + (2/H)*iy (exact)
    float qcx = -0.9921875f + 0.015625f * (float)ix;
    float rel0 = (p0 - qcy) * 128.0f;
    float rel1 = (p1 - qcx) * 128.0f;
    if (lane == 0) g_area[gw] = fabsf(rel0 * rel1) + 1e-9f;

    // cell quirk: points q==0 and q==1 are scaled by 2/32; rel_cell = cell*[H,W]
    float cellscale = (q < 2) ? 8.0f : 128.0f;

    size_t base = ((size_t)(b * HW_ + iy * W_ + ix)) * N_CONV;
    float* urow = g_U + (size_t)gw * 256;
#pragma unroll
    for (int j = 0; j < 4; j++) {
        int k = lane + 32 * j;
        float2 fr = *reinterpret_cast<const float2*>(&g_convout[base + 256 + 2 * k]);
        float2 pw = *reinterpret_cast<const float2*>(&phase_w[2 * k]);
        float f = fr.x * rel0 + fr.y * rel1 + (cellscale * pw.x + cellscale * pw.y);
        float sv, cv;
        sincospif(f, &sv, &cv);
        urow[k]       = g_convout[base + k]       * cv;
        urow[k + 128] = g_convout[base + 128 + k] * sv;
    }
}

// ---------------------------------------------------------------------------
// K5: final layer [M,256] @ w3[256,2] + b3 -> pred.  One warp per row.
// ---------------------------------------------------------------------------
__global__ void final_layer_kernel(const float* __restrict__ Vv,
                                   const float* __restrict__ w3,
                                   const float* __restrict__ b3)
{
    int gw = (blockIdx.x * blockDim.x + threadIdx.x) >> 5;
    int lane = threadIdx.x & 31;
    if (gw >= M_MLP) return;
    const float* v = Vv + (size_t)gw * 256;
    float a0 = 0.0f, a1 = 0.0f;
#pragma unroll
    for (int j = 0; j < 8; j++) {
        int k = lane + 32 * j;
        float x = v[k];
        a0 = fmaf(x, w3[2 * k + 0], a0);
        a1 = fmaf(x, w3[2 * k + 1], a1);
    }
#pragma unroll
    for (int off = 16; off > 0; off >>= 1) {
        a0 += __shfl_down_sync(0xFFFFFFFFu, a0, off);
        a1 += __shfl_down_sync(0xFFFFFFFFu, a1, off);
    }
    if (lane == 0) {
        g_pred[(size_t)gw * 2 + 0] = a0 + b3[0];
        g_pred[(size_t)gw * 2 + 1] = a1 + b3[1];
    }
}

// ---------------------------------------------------------------------------
// K6: local-ensemble combine (areas diagonally swapped) + coarse add.
// ---------------------------------------------------------------------------
__global__ void ensemble_kernel(const float* __restrict__ coarse, float* __restrict__ out)
{
    int t = blockIdx.x * blockDim.x + threadIdx.x;
    if (t >= B_ * Q_) return;
    int q = t & (Q_ - 1);
    int b = t >> 15;
    float a[4];
#pragma unroll
    for (int s = 0; s < 4; s++) a[s] = g_area[s * (B_ * Q_) + b * Q_ + q];
    float tot = a[0] + a[1] + a[2] + a[3];
    float r0 = 0.0f, r1 = 0.0f;
#pragma unroll
    for (int s = 0; s < 4; s++) {
        float w = a[3 - s] / tot;
        const float* p = g_pred + ((size_t)(s * (B_ * Q_) + b * Q_ + q)) * 2;
        r0 += p[0] * w;
        r1 += p[1] * w;
    }
    out[(size_t)(b * 2 + 0) * Q_ + q] = r0 + coarse[(size_t)(b * 2 + 0) * Q_ + q];
    out[(size_t)(b * 2 + 1) * Q_ + q] = r1 + coarse[(size_t)(b * 2 + 1) * Q_ + q];
}

// ---------------------------------------------------------------------------
// Launch
// ---------------------------------------------------------------------------
extern "C" void kernel_launch(void* const* d_in, const int* in_sizes, int n_in,
                              void* d_out, int out_size)
{
    const float* feat    = (const float*)d_in[0];
    const float* pc      = (const float*)d_in[1];
    const float* coarse  = (const float*)d_in[2];
    // d_in[3] coarse_sem_seg_logits: only its (32,32) shape matters (constants)
    const float* coef_w  = (const float*)d_in[4];
    const float* coef_b  = (const float*)d_in[5];
    const float* freq_w  = (const float*)d_in[6];
    const float* freq_b  = (const float*)d_in[7];
    const float* phase_w = (const float*)d_in[8];
    const float* w0 = (const float*)d_in[9];  const float* b0 = (const float*)d_in[10];
    const float* w1 = (const float*)d_in[11]; const float* b1 = (const float*)d_in[12];
    const float* w2 = (const float*)d_in[13]; const float* b2 = (const float*)d_in[14];
    const float* w3 = (const float*)d_in[15]; const float* b3 = (const float*)d_in[16];
    float* out = (float*)d_out;

    void *p_wconv, *p_bconv, *p_col, *p_convout, *p_U, *p_V;
    cudaGetSymbolAddress(&p_wconv,   g_wconv);
    cudaGetSymbolAddress(&p_bconv,   g_bconv);
    cudaGetSymbolAddress(&p_col,     g_col);
    cudaGetSymbolAddress(&p_convout, g_convout);
    cudaGetSymbolAddress(&p_U,       g_U);
    cudaGetSymbolAddress(&p_V,       g_V);

    // K0: weight transpose/combine
    prep_weights_kernel<<<(K_CONV * N_CONV + 255) / 256, 256>>>(coef_w, coef_b, freq_w, freq_b);
    // K1: im2col
    im2col_kernel<<<(M_CONV * C_) / 256, 256>>>(feat);
    // K2: conv GEMM -> [pixel][coef(256)|freq(256)]
    sgemm_kernel<<<dim3(N_CONV / 128, M_CONV / 128), 256>>>(
        (const float*)p_col, (const float*)p_wconv, (const float*)p_bconv,
        (float*)p_convout, M_CONV, N_CONV, K_CONV, 0);
    // K3: build X rows (writes g_U, g_area)
    prepare_kernel<<<(M_MLP * 32) / 256, 256>>>(pc, phase_w);
    // K4: MLP hidden layers
    sgemm_kernel<<<dim3(2, M_MLP / 128), 256>>>((const float*)p_U, w0, b0, (float*)p_V,
                                                M_MLP, 256, 256, 1);
    sgemm_kernel<<<dim3(2, M_MLP / 128), 256>>>((const float*)p_V, w1, b1, (float*)p_U,
                                                M_MLP, 256, 256, 1);
    sgemm_kernel<<<dim3(2, M_MLP / 128), 256>>>((const float*)p_U, w2, b2, (float*)p_V,
                                                M_MLP, 256, 256, 1);
    // K5: final 256->2
    final_layer_kernel<<<(M_MLP * 32) / 256, 256>>>((const float*)p_V, w3, b3);
    // K6: ensemble + coarse
    ensemble_kernel<<<(B_ * Q_) / 256, 256>>>(coarse, out);
}